// round 16
// baseline (speedup 1.0000x reference)
#include <cuda_runtime.h>
#include <cstdint>
#include <math.h>

// BaseSmear: project 64^3 grid points into 8 camera images, nearest-neighbor
// gather of 32 feature channels + depth + validity + ray direction.
//
// SINGLE persistent kernel (grid 592 = 4 blocks/SM, all resident):
//   phase 1: strided transpose tiles [C,HW]->[HW,C] (round-15 inner loop),
//            per-image completion counters (release-fenced atomics).
//   phase 2: strided smear tiles (round-15 inner loop), gated per image on
//            the counter (acquire-fenced spin). No launch gaps, early blocks
//            overlap smear(im0) with straggling transposes of im1..7.
//   Counters self-reset by the last finishing block -> graph-replay safe.

#define II 8
#define CC 32
#define HH 240
#define WW 320
#define HW (HH*WW)          // 76800
#define NN (64*64*64)       // 262144
#define NN4 (NN/4)          // 65536
#define GRID 592            // 148 SMs * 4 blocks (guaranteed resident)
#define TTILES (II * 600)   // 4800 transpose tiles (128 pixels each)
#define STILES (II * 1024)  // 8192 smear tiles (256 points each)

__device__ float g_imgT[(size_t)II * HW * CC];   // 78.6 MB channels-last scratch
__device__ int   g_tcnt[II];                     // transpose tiles done per image
__device__ int   g_done;                         // blocks finished

__global__ __launch_bounds__(256, 4) void fused_kernel(
    const float* __restrict__ images,   // [8,32,240,320]
    const float* __restrict__ trans,    // [8,3,4]
    const float* __restrict__ Tcw,      // [8,4,4]
    const float* __restrict__ coords,   // [3,64,64,64]
    float* __restrict__ out)            // [8,37,N] then [3,N]
{
    __shared__ float s[8192];           // 32 KB, reused by both phases

    const int tid  = threadIdx.x;
    const int lane = tid & 31;
    const int wrp  = tid >> 5;
    const int bid  = blockIdx.x;

    // ===================== Phase 1: transpose tiles =====================
    for (int tt = bid; tt < TTILES; tt += GRID) {
        const int img     = tt / 600;
        const int pixbase = (tt % 600) * 128;

        // load: thread (c = tid>>3, l8 = tid&7), 4 x LDG.128.
        {
            const int c  = tid >> 3;
            const int l8 = tid & 7;
            const float4* src = (const float4*)(images + (size_t)img * CC * HW
                                                + (size_t)c * HW + pixbase);
            float* srow = &s[c * 129];
            #pragma unroll
            for (int r = 0; r < 4; r++) {
                const int k = l8 + 8 * r;
                const float4 v = __ldcs(src + k);
                srow[4 * k + 0] = v.x;
                srow[4 * k + 1] = v.y;
                srow[4 * k + 2] = v.z;
                srow[4 * k + 3] = v.w;
            }
        }
        __syncthreads();

        // store: 4 pixels x 128B contiguous per instr (4 full lines).
        {
            const int seg  = lane & 7;
            const int pix4 = lane >> 3;
            float4* dst = (float4*)(g_imgT + ((size_t)img * HW + pixbase) * CC) + seg;
            #pragma unroll
            for (int r = 0; r < 4; r++) {
                const int p = 16 * wrp + 4 * r + pix4;
                float4 v;
                v.x = s[(4 * seg + 0) * 129 + p];
                v.y = s[(4 * seg + 1) * 129 + p];
                v.z = s[(4 * seg + 2) * 129 + p];
                v.w = s[(4 * seg + 3) * 129 + p];
                dst[(size_t)p * 8] = v;
            }
        }
        __syncthreads();                 // all stores of this tile issued
        if (tid == 0) {
            __threadfence();             // release: tile visible before count
            atomicAdd(&g_tcnt[img], 1);
        }
        __syncthreads();                 // s free for next tile
    }

    // ===================== Phase 2: smear tiles =========================
    int readyImg = -1;
    for (int st = bid; st < STILES; st += GRID) {
        const int i  = st >> 10;
        const int nb = (st & 1023) << 8;
        const int n  = nb + tid;

        // gate: wait until image i fully transposed (monotone per block)
        if (i > readyImg) {
            if (tid == 0) {
                while (atomicAdd(&g_tcnt[i], 0) < 600) __nanosleep(128);
            }
            __syncthreads();
            if (tid == 0) __threadfence();   // acquire for transposed data
            __syncthreads();
            readyImg = i;
        }

        // ---------- projection ----------
        const float px = coords[n];
        const float py = coords[NN + n];
        const float pz = coords[2 * NN + n];

        const float* T = Tcw   + i * 16;
        const float* P = trans + i * 12;

        const float depth = T[8] * px + T[9] * py + T[10] * pz + T[11];
        const float w  = P[8] * px + P[9] * py + P[10] * pz + P[11];
        const float ws = (fabsf(w) < 1e-8f) ? 1e-8f : w;
        const float u  = (P[0] * px + P[1] * py + P[2] * pz + P[3]) / ws;
        const float v  = (P[4] * px + P[5] * py + P[6] * pz + P[7]) / ws;

        const bool valid = (u >= 0.0f) && (u <= (float)(WW - 1)) &&
                           (v >= 0.0f) && (v <= (float)(HH - 1)) &&
                           (depth > 0.0f);
        const float validf = valid ? 1.0f : 0.0f;

        const int ui = (int)fminf(fmaxf(rintf(u), 0.0f), (float)(WW - 1));
        const int vi = (int)fminf(fmaxf(rintf(v), 0.0f), (float)(HH - 1));
        const int poffEnc = valid ? (vi * WW + ui) : -1;

        // ---------- hoisted cooperative gather (MLP = 8) ----------
        const int chunk = lane & 7;
        const int ptoff = lane >> 3;

        const float* imgBase = g_imgT + (size_t)i * HW * CC + chunk * 4;
        const float4 z4 = make_float4(0.f, 0.f, 0.f, 0.f);

        float4 f[8];
        #pragma unroll
        for (int it = 0; it < 8; it++) {
            const int pe = __shfl_sync(0xffffffffu, poffEnc, it * 4 + ptoff);
            f[it] = z4;
            if (pe >= 0)
                f[it] = __ldg((const float4*)(imgBase + (size_t)pe * CC));
        }

        // ---------- extras + coords (fills the gather latency) ----------
        {
            const float ccx = -(T[0] * T[3] + T[4] * T[7] + T[8]  * T[11]);
            const float ccy = -(T[1] * T[3] + T[5] * T[7] + T[9]  * T[11]);
            const float ccz = -(T[2] * T[3] + T[6] * T[7] + T[10] * T[11]);
            float dx = px - ccx, dy = py - ccy, dz = pz - ccz;
            const float inv = 1.0f / (sqrtf(dx * dx + dy * dy + dz * dz) + 1e-8f);

            float* eo = out + (size_t)i * 37 * NN + n;
            __stcs(eo + (size_t)32 * NN, depth);
            __stcs(eo + (size_t)33 * NN, validf);
            __stcs(eo + (size_t)34 * NN, dx * inv);
            __stcs(eo + (size_t)35 * NN, dy * inv);
            __stcs(eo + (size_t)36 * NN, dz * inv);
            if (i == 0) {
                float* tail = out + (size_t)II * 37 * NN;
                __stcs(tail + n,          px);
                __stcs(tail + NN + n,     py);
                __stcs(tail + 2 * NN + n, pz);
            }
        }

        // ---------- drain gathers into warp-local swizzled smem ----------
        const int ch = chunk * 4;
        float* sw = &s[wrp * 1024];
        #pragma unroll
        for (int it = 0; it < 8; it++) {
            const int q = it * 4 + ptoff;
            const int base = ch * 32 + (q ^ (chunk * 4));
            sw[base]      = f[it].x;
            sw[base + 32] = f[it].y;
            sw[base + 64] = f[it].z;
            sw[base + 96] = f[it].w;
        }

        __syncwarp();

        // ---------- warp-local coalesced float4 streamed output ----------
        float4* o4 = (float4*)out + (size_t)i * 37 * NN4 + (nb >> 2) + wrp * 8;
        #pragma unroll
        for (int r = 0; r < 8; r++) {
            const int c  = r * 4 + (lane >> 3);
            const int qq = lane & 7;
            const float4 val = *(const float4*)&sw[c * 32 + ((qq * 4) ^ (c & 28))];
            __stcs(&o4[(size_t)c * NN4 + qq], val);
        }

        __syncwarp();                    // slab reused next tile
    }

    // ===================== epilogue: counter reset ======================
    __syncthreads();
    if (tid == 0) {
        __threadfence();
        if (atomicAdd(&g_done, 1) == GRID - 1) {   // last block restores state
            #pragma unroll
            for (int k = 0; k < II; k++) g_tcnt[k] = 0;
            __threadfence();
            g_done = 0;
        }
    }
}

extern "C" void kernel_launch(void* const* d_in, const int* in_sizes, int n_in,
                              void* d_out, int out_size) {
    const float* images = (const float*)d_in[0];
    const float* trans  = (const float*)d_in[1];
    const float* Tcw    = (const float*)d_in[2];
    const float* coords = (const float*)d_in[3];
    float* out = (float*)d_out;

    fused_kernel<<<GRID, 256>>>(images, trans, Tcw, coords, out);
}

// round 17
// speedup vs baseline: 1.2980x; 1.2980x over previous
#include <cuda_runtime.h>
#include <cuda_fp16.h>
#include <cstdint>
#include <math.h>

// BaseSmear: project 64^3 grid points into 8 camera images, nearest-neighbor
// gather of 32 feature channels + depth + validity + ray direction.
//
//   1) transpose+convert [I,C,H,W] fp32 -> [I,H,W,C] fp16 scratch (39 MB,
//      fully L2-resident; halves transpose write + gather read traffic).
//      fp16 rel-err <= 2^-11 ~ 4.9e-4, under the 1e-3 threshold.
//   2) smear: per-thread projection; cooperative gather (4 lanes share one
//      pixel's 64B fp16 channel vector, 8 pixels per LDG.128, offsets via
//      SHFL, loads hoisted); convert-on-STS into the proven fp32 swizzled
//      warp-local stage; STG.128 + __stcs streamed output.

#define II 8
#define CC 32
#define HH 240
#define WW 320
#define HW (HH*WW)          // 76800
#define NN (64*64*64)       // 262144
#define NN4 (NN/4)          // 65536

__device__ __half g_imgTh[(size_t)II * HW * CC];   // 39.3 MB fp16 channels-last

// ---- Phase 1: [C, HW] fp32 -> [HW, C] fp16 transpose -----------------------
// block: 256 threads, tile: 32 channels x 128 pixels. grid = II * (HW/128).
__global__ __launch_bounds__(256) void transpose_kernel(const float* __restrict__ images) {
    __shared__ float s[32 * 129];                    // stride 129: 16.5 KB

    const int tilesPerImg = HW / 128;                // 600
    const int i       = blockIdx.x / tilesPerImg;
    const int pixbase = (blockIdx.x % tilesPerImg) * 128;
    const int t = threadIdx.x;

    // load: thread (c = t>>3, l8 = t&7), 4 x LDG.128 (4 full lines per instr)
    {
        const int c  = t >> 3;                       // 0..31
        const int l8 = t & 7;                        // 0..7
        const float4* src = (const float4*)(images + (size_t)i * CC * HW
                                            + (size_t)c * HW + pixbase);
        float* srow = &s[c * 129];
        #pragma unroll
        for (int r = 0; r < 4; r++) {
            const int k = l8 + 8 * r;                // float4 index 0..31
            const float4 v = __ldcs(src + k);
            srow[4 * k + 0] = v.x;
            srow[4 * k + 1] = v.y;
            srow[4 * k + 2] = v.z;
            srow[4 * k + 3] = v.w;
        }
    }
    __syncthreads();

    // store: fp16 pack. lanes = (seg = lane&3 of the 64B pixel vec,
    // pix8 = lane>>2). per instr: 8 pixels x 64B = 512B contiguous = 4 lines.
    {
        const int lane = t & 31;
        const int wrp  = t >> 5;
        const int seg  = lane & 3;                   // 16B segment (8 channels)
        const int pix8 = lane >> 2;                  // 0..7
        uint4* dstBase = (uint4*)(g_imgTh + ((size_t)i * HW + pixbase) * CC);
        #pragma unroll
        for (int r = 0; r < 2; r++) {
            const int p = 16 * wrp + 8 * r + pix8;   // pixel 0..127
            // bank = (8*seg + d + p) mod 32 -> distinct across lanes
            const int cb = 8 * seg;
            __half2 h0 = __floats2half2_rn(s[(cb + 0) * 129 + p], s[(cb + 1) * 129 + p]);
            __half2 h1 = __floats2half2_rn(s[(cb + 2) * 129 + p], s[(cb + 3) * 129 + p]);
            __half2 h2 = __floats2half2_rn(s[(cb + 4) * 129 + p], s[(cb + 5) * 129 + p]);
            __half2 h3 = __floats2half2_rn(s[(cb + 6) * 129 + p], s[(cb + 7) * 129 + p]);
            uint4 v;
            v.x = *reinterpret_cast<uint32_t*>(&h0);
            v.y = *reinterpret_cast<uint32_t*>(&h1);
            v.z = *reinterpret_cast<uint32_t*>(&h2);
            v.w = *reinterpret_cast<uint32_t*>(&h3);
            dstBase[p * 4 + seg] = v;                // keep in L2 (no stcs)
        }
    }
}

// ---- Phase 2: project + fp16 coop gather + fp32 swizzled stage + STG.128 ---
__global__ __launch_bounds__(256, 4) void smear_kernel(
    const float* __restrict__ trans,    // [8,3,4]
    const float* __restrict__ Tcw,      // [8,4,4]
    const float* __restrict__ coords,   // [3,64,64,64]
    float* __restrict__ out)            // [8,37,N] then [3,N]
{
    __shared__ float s[8][32 * 32];     // 4 KB per warp (fp32 stage)

    const int tid  = threadIdx.x;
    const int lane = tid & 31;
    const int wrp  = tid >> 5;
    const int bid  = blockIdx.x;
    const int i    = bid >> 10;              // 1024 blocks per image
    const int nb   = (bid & 1023) << 8;      // block's base point
    const int n    = nb + tid;

    // ---------- Phase A: per-thread projection ----------
    const float px = coords[n];
    const float py = coords[NN + n];
    const float pz = coords[2 * NN + n];

    const float* T = Tcw   + i * 16;
    const float* P = trans + i * 12;

    const float depth = T[8] * px + T[9] * py + T[10] * pz + T[11];
    const float w  = P[8] * px + P[9] * py + P[10] * pz + P[11];
    const float ws = (fabsf(w) < 1e-8f) ? 1e-8f : w;
    const float u  = (P[0] * px + P[1] * py + P[2] * pz + P[3]) / ws;
    const float v  = (P[4] * px + P[5] * py + P[6] * pz + P[7]) / ws;

    const bool valid = (u >= 0.0f) && (u <= (float)(WW - 1)) &&
                       (v >= 0.0f) && (v <= (float)(HH - 1)) &&
                       (depth > 0.0f);
    const float validf = valid ? 1.0f : 0.0f;

    const int ui = (int)fminf(fmaxf(rintf(u), 0.0f), (float)(WW - 1));
    const int vi = (int)fminf(fmaxf(rintf(v), 0.0f), (float)(HH - 1));
    const int poffEnc = valid ? (vi * WW + ui) : -1;

    // ---------- Phase B1: hoisted cooperative gather (fp16, 4 lanes/pixel) --
    const int chunk = lane & 3;              // which 16B of the 64B pixel vec
    const int ptoff = lane >> 2;             // which of 8 points this instr

    const uint4* imgBase = (const uint4*)(g_imgTh + (size_t)i * HW * CC);
    const uint4 z4 = make_uint4(0u, 0u, 0u, 0u);

    uint4 f[4];
    #pragma unroll
    for (int it = 0; it < 4; it++) {
        const int pe = __shfl_sync(0xffffffffu, poffEnc, it * 8 + ptoff);
        f[it] = z4;
        if (pe >= 0)
            f[it] = __ldg(imgBase + (size_t)pe * 4 + chunk);
    }

    // ---------- Phase A2: extras + coords (fills the gather latency) --------
    {
        const float ccx = -(T[0] * T[3] + T[4] * T[7] + T[8]  * T[11]);
        const float ccy = -(T[1] * T[3] + T[5] * T[7] + T[9]  * T[11]);
        const float ccz = -(T[2] * T[3] + T[6] * T[7] + T[10] * T[11]);
        float dx = px - ccx, dy = py - ccy, dz = pz - ccz;
        const float inv = 1.0f / (sqrtf(dx * dx + dy * dy + dz * dz) + 1e-8f);

        float* eo = out + (size_t)i * 37 * NN + n;
        __stcs(eo + (size_t)32 * NN, depth);
        __stcs(eo + (size_t)33 * NN, validf);
        __stcs(eo + (size_t)34 * NN, dx * inv);
        __stcs(eo + (size_t)35 * NN, dy * inv);
        __stcs(eo + (size_t)36 * NN, dz * inv);
        if (i == 0) {
            float* tail = out + (size_t)II * 37 * NN;
            __stcs(tail + n,          px);
            __stcs(tail + NN + n,     py);
            __stcs(tail + 2 * NN + n, pz);
        }
    }

    // ---------- Phase B2: convert + drain into warp-local swizzled smem -----
    // channels 8*chunk .. 8*chunk+7; layout s[ch*32 + (q ^ (ch&28))]
    float* sw = s[wrp];
    #pragma unroll
    for (int it = 0; it < 4; it++) {
        const int q = it * 8 + ptoff;        // point index within warp (0..31)
        const __half2* hp = reinterpret_cast<const __half2*>(&f[it]);
        #pragma unroll
        for (int d2 = 0; d2 < 4; d2++) {
            const float2 fv = __half22float2(hp[d2]);
            const int ch = 8 * chunk + 2 * d2;
            const int sx = ch * 32 + (q ^ (ch & 28));        // even ch
            sw[sx]      = fv.x;
            sw[sx + 32] = fv.y;              // ch+1: same (ch&28), next row
        }
    }

    __syncwarp();

    // ---------- Phase C: warp-local coalesced float4 streamed output ----------
    float4* o4 = (float4*)out + (size_t)i * 37 * NN4 + (nb >> 2) + wrp * 8;
    #pragma unroll
    for (int r = 0; r < 8; r++) {
        const int c  = r * 4 + (lane >> 3);  // channel 0..31
        const int qq = lane & 7;             // float4 index within warp (0..7)
        const float4 val = *(const float4*)&sw[c * 32 + ((qq * 4) ^ (c & 28))];
        __stcs(&o4[(size_t)c * NN4 + qq], val);
    }
}

extern "C" void kernel_launch(void* const* d_in, const int* in_sizes, int n_in,
                              void* d_out, int out_size) {
    const float* images = (const float*)d_in[0];
    const float* trans  = (const float*)d_in[1];
    const float* Tcw    = (const float*)d_in[2];
    const float* coords = (const float*)d_in[3];
    float* out = (float*)d_out;

    transpose_kernel<<<II * (HW / 128), 256>>>(images);
    smear_kernel<<<II * (NN / 256), 256>>>(trans, Tcw, coords, out);
}